// round 2
// baseline (speedup 1.0000x reference)
#include <cuda_runtime.h>

#define NN 50000
#define NE 600000
#define NG 500
#define HID 128
#define NL 3
#define NC 10

// ---------------- scratch (device globals; no runtime allocation) ----------------
__device__ float g_mean[NN * HID];
__device__ float g_x1[NN * HID];
__device__ float g_x2[NN * HID];
__device__ float g_pool[NG * HID];
__device__ float g_h[NG * HID];
__device__ int   g_deg[NN];
__device__ int   g_off[NN + 1];
__device__ int   g_cur[NN];
__device__ int   g_srcs[NE];

// ---------------- CSR build ----------------
__global__ void zero_kernel() {
    int i = blockIdx.x * blockDim.x + threadIdx.x;
    if (i < NN) g_deg[i] = 0;
    if (i < NG * HID) g_pool[i] = 0.f;
}

__global__ void count_kernel(const int* __restrict__ ei) {
    int e = blockIdx.x * blockDim.x + threadIdx.x;
    if (e >= NE) return;
    atomicAdd(&g_deg[ei[NE + e]], 1);
}

// single-block exclusive scan over 50000 degrees
__global__ void scan_kernel() {
    __shared__ int ssum[1024];
    const int tid = threadIdx.x;
    const int CH = (NN + 1023) / 1024;  // 49
    const int base = tid * CH;
    int s = 0;
    for (int i = 0; i < CH; i++) {
        int idx = base + i;
        if (idx < NN) s += g_deg[idx];
    }
    ssum[tid] = s;
    __syncthreads();
    // Hillis-Steele inclusive scan
    for (int ofs = 1; ofs < 1024; ofs <<= 1) {
        int v = (tid >= ofs) ? ssum[tid - ofs] : 0;
        __syncthreads();
        ssum[tid] += v;
        __syncthreads();
    }
    int run = ssum[tid] - s;  // exclusive base of this chunk
    for (int i = 0; i < CH; i++) {
        int idx = base + i;
        if (idx < NN) {
            g_off[idx] = run;
            g_cur[idx] = run;
            run += g_deg[idx];
        }
    }
    if (tid == 1023) g_off[NN] = ssum[1023];
}

__global__ void bucket_kernel(const int* __restrict__ ei) {
    int e = blockIdx.x * blockDim.x + threadIdx.x;
    if (e >= NE) return;
    int src = ei[e];
    int dst = ei[NE + e];
    int pos = atomicAdd(&g_cur[dst], 1);
    g_srcs[pos] = src;
}

// ---------------- mean aggregation: one warp per node ----------------
__global__ void aggregate_kernel(const float4* __restrict__ x) {
    int w = (blockIdx.x * blockDim.x + threadIdx.x) >> 5;
    int lane = threadIdx.x & 31;
    if (w >= NN) return;
    int s0 = g_off[w], s1 = g_off[w + 1];
    float4 a = make_float4(0.f, 0.f, 0.f, 0.f);
    for (int e = s0; e < s1; e++) {
        int s = __ldg(&g_srcs[e]);
        float4 v = __ldg(&x[(long)s * 32 + lane]);
        a.x += v.x; a.y += v.y; a.z += v.z; a.w += v.w;
    }
    float inv = 1.f / (float)max(s1 - s0, 1);
    float4 r = make_float4(a.x * inv, a.y * inv, a.z * inv, a.w * inv);
    reinterpret_cast<float4*>(g_mean)[(long)w * 32 + lane] = r;
}

// ---------------- fused SAGE GEMM: out = relu(mean@Wl^T + bl + x@Wr^T) ----------------
// Weights staged transposed in dynamic smem; 8-node tiles; 256 threads.
__global__ void __launch_bounds__(256) sage_gemm_kernel(
    const float* __restrict__ mean, const float* __restrict__ xin,
    const float* __restrict__ Wl, const float* __restrict__ bl,
    const float* __restrict__ Wr, float* __restrict__ out)
{
    extern __shared__ float smw[];
    float* Sl = smw;             // [k][j]
    float* Sr = smw + HID * HID; // [k][j]
    __shared__ float sb[HID];
    __shared__ __align__(16) float sm_mean[HID * 8]; // [k][node]
    __shared__ __align__(16) float sm_x[HID * 8];

    for (int idx = threadIdx.x; idx < HID * HID; idx += 256) {
        int j = idx >> 7, k = idx & 127;
        Sl[k * HID + j] = Wl[idx];
        Sr[k * HID + j] = Wr[idx];
    }
    if (threadIdx.x < HID) sb[threadIdx.x] = bl[threadIdx.x];
    __syncthreads();

    const int j = threadIdx.x & 127;
    const int half = threadIdx.x >> 7;  // 0 or 1
    const int NT = NN / 8;              // 6250 tiles, exact

    for (int tile = blockIdx.x; tile < NT; tile += gridDim.x) {
        int base = tile * 8;
        __syncthreads();
        for (int idx = threadIdx.x; idx < 8 * HID; idx += 256) {
            int r = idx >> 7, k = idx & 127;
            sm_mean[k * 8 + r] = mean[(base + r) * HID + k];
            sm_x[k * 8 + r]   = xin[(base + r) * HID + k];
        }
        __syncthreads();

        float a0 = sb[j], a1 = sb[j], a2 = sb[j], a3 = sb[j];
#pragma unroll 8
        for (int k = 0; k < HID; k++) {
            float wl = Sl[k * HID + j];
            float wr = Sr[k * HID + j];
            float4 m  = *reinterpret_cast<const float4*>(&sm_mean[k * 8 + half * 4]);
            float4 xv = *reinterpret_cast<const float4*>(&sm_x[k * 8 + half * 4]);
            a0 += m.x * wl + xv.x * wr;
            a1 += m.y * wl + xv.y * wr;
            a2 += m.z * wl + xv.z * wr;
            a3 += m.w * wl + xv.w * wr;
        }
        int n0 = base + half * 4;
        out[(n0 + 0) * HID + j] = fmaxf(a0, 0.f);
        out[(n0 + 1) * HID + j] = fmaxf(a1, 0.f);
        out[(n0 + 2) * HID + j] = fmaxf(a2, 0.f);
        out[(n0 + 3) * HID + j] = fmaxf(a3, 0.f);
    }
}

// ---------------- global add pool ----------------
__global__ void pool_kernel(const float* __restrict__ xf, const int* __restrict__ batch) {
    int i = blockIdx.x * blockDim.x + threadIdx.x;  // over NN*HID
    if (i >= NN * HID) return;
    int n = i >> 7, k = i & 127;
    int b = batch[n];
    atomicAdd(&g_pool[b * HID + k], xf[i]);
}

// ---------------- MLP head ----------------
__global__ void mlp1_kernel(const float* __restrict__ W1, const float* __restrict__ b1) {
    int b = blockIdx.x;
    int j = threadIdx.x;
    __shared__ float sg[HID];
    sg[j] = fmaxf(g_pool[b * HID + j], 0.f);  // relu(pool)
    __syncthreads();
    float a = b1[j];
    const float* wrow = &W1[j * HID];
#pragma unroll 8
    for (int k = 0; k < HID; k++) a += sg[k] * wrow[k];
    g_h[b * HID + j] = fmaxf(a, 0.f);
}

__global__ void mlp2_kernel(const float* __restrict__ W2, const float* __restrict__ b2,
                            float* __restrict__ out) {
    int b = blockIdx.x;
    __shared__ float sh[HID];
    __shared__ float slog[NC];
    int tid = threadIdx.x;
    if (tid < HID) sh[tid] = g_h[b * HID + tid];
    __syncthreads();
    int w = tid >> 5, lane = tid & 31;
    if (w < NC) {
        float a = 0.f;
        for (int k = lane; k < HID; k += 32) a += sh[k] * W2[w * HID + k];
#pragma unroll
        for (int o = 16; o; o >>= 1) a += __shfl_down_sync(0xffffffffu, a, o);
        if (lane == 0) slog[w] = a + b2[w];
    }
    __syncthreads();
    if (tid < NC) {
        float mx = -1e30f;
#pragma unroll
        for (int c = 0; c < NC; c++) mx = fmaxf(mx, slog[c]);
        float se = 0.f;
#pragma unroll
        for (int c = 0; c < NC; c++) se += expf(slog[c] - mx);
        out[b * NC + tid] = slog[tid] - mx - logf(se);
    }
}

// ---------------- launch ----------------
extern "C" void kernel_launch(void* const* d_in, const int* in_sizes, int n_in,
                              void* d_out, int out_size) {
    const float* x     = (const float*)d_in[0];
    // d_in[1] = edge_attr (ignored by SAGEConv)
    const int*   ei    = (const int*)d_in[2];
    const int*   batch = (const int*)d_in[3];
    const float* Wl    = (const float*)d_in[4];
    const float* bl    = (const float*)d_in[5];
    const float* Wr    = (const float*)d_in[6];
    const float* W1    = (const float*)d_in[7];
    const float* b1    = (const float*)d_in[8];
    const float* W2    = (const float*)d_in[9];
    const float* b2    = (const float*)d_in[10];
    float* out = (float*)d_out;

    float *mean_p, *x1_p, *x2_p;
    cudaGetSymbolAddress((void**)&mean_p, g_mean);
    cudaGetSymbolAddress((void**)&x1_p, g_x1);
    cudaGetSymbolAddress((void**)&x2_p, g_x2);

    const int SMEM_W = 2 * HID * HID * (int)sizeof(float);  // 128 KB
    cudaFuncSetAttribute(sage_gemm_kernel, cudaFuncAttributeMaxDynamicSharedMemorySize, SMEM_W);

    // CSR build (once per launch, reused across layers)
    zero_kernel<<<(NG * HID + 255) / 256, 256>>>();
    count_kernel<<<(NE + 255) / 256, 256>>>(ei);
    scan_kernel<<<1, 1024>>>();
    bucket_kernel<<<(NE + 255) / 256, 256>>>(ei);

    const float* cur = x;
    float* nxt = x1_p;
    for (int l = 0; l < NL; l++) {
        aggregate_kernel<<<(NN * 32 + 255) / 256, 256>>>((const float4*)cur);
        sage_gemm_kernel<<<148, 256, SMEM_W>>>(mean_p, cur,
                                               Wl + l * HID * HID, bl + l * HID,
                                               Wr + l * HID * HID, nxt);
        cur = nxt;
        nxt = (cur == x1_p) ? x2_p : x1_p;
    }

    pool_kernel<<<(NN * HID + 255) / 256, 256>>>(cur, batch);
    mlp1_kernel<<<NG, HID>>>(W1, b1);
    mlp2_kernel<<<NG, 320>>>(W2, b2, out);
}

// round 3
// speedup vs baseline: 1.4611x; 1.4611x over previous
#include <cuda_runtime.h>

#define NN 50000
#define NE 600000
#define NG 500
#define HID 128
#define NL 3
#define NC 10

#define TN 32          // gemm tile nodes
#define PADI 36        // staged-input row pad (floats)
#define PADW 130       // staged-weight row pad (floats)

typedef unsigned long long u64;

// ---------------- scratch ----------------
__device__ float g_mean[NN * HID];
__device__ float g_x1[NN * HID];
__device__ float g_x2[NN * HID];
__device__ float g_pool[NG * HID];
__device__ float g_h[NG * HID];
__device__ int   g_deg[NN];
__device__ int   g_off[NN + 1];
__device__ int   g_cur[NN];
__device__ int   g_srcs[NE];
__device__ int   g_gcnt[NG];
__device__ int   g_goff[NG + 1];

// ---------------- f32x2 helpers ----------------
__device__ __forceinline__ u64 pack2(float a) {
    u64 r; asm("mov.b64 %0, {%1, %1};" : "=l"(r) : "f"(a)); return r;
}
__device__ __forceinline__ u64 fma2(u64 a, u64 b, u64 c) {
    u64 d; asm("fma.rn.f32x2 %0, %1, %2, %3;" : "=l"(d) : "l"(a), "l"(b), "l"(c)); return d;
}
__device__ __forceinline__ void unpack2(u64 v, float& lo, float& hi) {
    asm("mov.b64 {%0, %1}, %2;" : "=f"(lo), "=f"(hi) : "l"(v));
}

// ---------------- CSR build ----------------
__global__ void zero_kernel() {
    int i = blockIdx.x * blockDim.x + threadIdx.x;
    if (i < NN) g_deg[i] = 0;
    if (i < NG) g_gcnt[i] = 0;
}

__global__ void count_kernel(const int* __restrict__ ei) {
    int e = blockIdx.x * blockDim.x + threadIdx.x;
    if (e >= NE) return;
    atomicAdd(&g_deg[ei[NE + e]], 1);
}

__global__ void scan_kernel() {
    __shared__ int ssum[1024];
    const int tid = threadIdx.x;
    const int CH = (NN + 1023) / 1024;
    const int base = tid * CH;
    int s = 0;
    for (int i = 0; i < CH; i++) { int idx = base + i; if (idx < NN) s += g_deg[idx]; }
    ssum[tid] = s;
    __syncthreads();
    for (int ofs = 1; ofs < 1024; ofs <<= 1) {
        int v = (tid >= ofs) ? ssum[tid - ofs] : 0;
        __syncthreads();
        ssum[tid] += v;
        __syncthreads();
    }
    int run = ssum[tid] - s;
    for (int i = 0; i < CH; i++) {
        int idx = base + i;
        if (idx < NN) { g_off[idx] = run; g_cur[idx] = run; run += g_deg[idx]; }
    }
    if (tid == 1023) g_off[NN] = ssum[1023];
}

__global__ void bucket_kernel(const int* __restrict__ ei) {
    int e = blockIdx.x * blockDim.x + threadIdx.x;
    if (e >= NE) return;
    int src = ei[e];
    int dst = ei[NE + e];
    int pos = atomicAdd(&g_cur[dst], 1);
    g_srcs[pos] = src;
}

// ---------------- graph segment offsets (batch is sorted) ----------------
__global__ void gcount_kernel(const int* __restrict__ batch) {
    int n = blockIdx.x * blockDim.x + threadIdx.x;
    if (n >= NN) return;
    atomicAdd(&g_gcnt[batch[n]], 1);
}

__global__ void gscan_kernel() {
    __shared__ int s[512];
    int tid = threadIdx.x;
    int v = (tid < NG) ? g_gcnt[tid] : 0;
    s[tid] = v;
    __syncthreads();
    for (int ofs = 1; ofs < 512; ofs <<= 1) {
        int t = (tid >= ofs) ? s[tid - ofs] : 0;
        __syncthreads();
        s[tid] += t;
        __syncthreads();
    }
    if (tid < NG) g_goff[tid] = s[tid] - v;     // exclusive
    if (tid == NG - 1) g_goff[NG] = s[tid];
}

// ---------------- mean aggregation: one warp per node, MLP=4 ----------------
__global__ void aggregate_kernel(const float4* __restrict__ x) {
    int w = (blockIdx.x * blockDim.x + threadIdx.x) >> 5;
    int lane = threadIdx.x & 31;
    if (w >= NN) return;
    int s0 = g_off[w], s1 = g_off[w + 1];
    float4 a = make_float4(0.f, 0.f, 0.f, 0.f);
    int e = s0;
    for (; e + 4 <= s1; e += 4) {
        int i0 = __ldg(&g_srcs[e]);
        int i1 = __ldg(&g_srcs[e + 1]);
        int i2 = __ldg(&g_srcs[e + 2]);
        int i3 = __ldg(&g_srcs[e + 3]);
        float4 v0 = __ldg(&x[(long)i0 * 32 + lane]);
        float4 v1 = __ldg(&x[(long)i1 * 32 + lane]);
        float4 v2 = __ldg(&x[(long)i2 * 32 + lane]);
        float4 v3 = __ldg(&x[(long)i3 * 32 + lane]);
        a.x += (v0.x + v1.x) + (v2.x + v3.x);
        a.y += (v0.y + v1.y) + (v2.y + v3.y);
        a.z += (v0.z + v1.z) + (v2.z + v3.z);
        a.w += (v0.w + v1.w) + (v2.w + v3.w);
    }
    for (; e < s1; e++) {
        int s = __ldg(&g_srcs[e]);
        float4 v = __ldg(&x[(long)s * 32 + lane]);
        a.x += v.x; a.y += v.y; a.z += v.z; a.w += v.w;
    }
    float inv = 1.f / (float)max(s1 - s0, 1);
    float4 r = make_float4(a.x * inv, a.y * inv, a.z * inv, a.w * inv);
    reinterpret_cast<float4*>(g_mean)[(long)w * 32 + lane] = r;
}

// ---------------- fused SAGE GEMM with FFMA2 ----------------
// out[n][j] = relu( sum_k mean[n][k]*Wl[j][k] + bl[j] + sum_k x[n][k]*Wr[j][k] )
// 512 threads, 32-node tiles, 8 nodes/thread packed in 4 f32x2 accumulators.
__global__ void __launch_bounds__(512) sage_gemm_kernel(
    const float* __restrict__ mean, const float* __restrict__ xin,
    const float* __restrict__ Wl, const float* __restrict__ bl,
    const float* __restrict__ Wr, float* __restrict__ out)
{
    extern __shared__ float smw[];
    float* Sl = smw;                         // [k*PADW + j]
    float* Sr = Sl + HID * PADW;             // [k*PADW + j]
    float* SM = Sr + HID * PADW;             // [k*PADI + r]
    float* SX = SM + HID * PADI;             // [k*PADI + r]
    __shared__ float sb[HID];

    // stage weights transposed: Sl[k][j] = Wl[j][k]; write is 2-way conflict (pad 130)
    for (int idx = threadIdx.x; idx < HID * HID; idx += 512) {
        int j = idx >> 7, k = idx & 127;     // consecutive threads -> consecutive k (coalesced gmem)
        Sl[k * PADW + j] = Wl[idx];
        Sr[k * PADW + j] = Wr[idx];
    }
    if (threadIdx.x < HID) sb[threadIdx.x] = bl[threadIdx.x];
    __syncthreads();

    const int j = threadIdx.x & 127;
    const int grp = threadIdx.x >> 7;        // 0..3 -> nodes grp*8 .. grp*8+7
    const int NT = (NN + TN - 1) / TN;       // 1563

    for (int tile = blockIdx.x; tile < NT; tile += gridDim.x) {
        int base = tile * TN;
        __syncthreads();
        for (int idx = threadIdx.x; idx < TN * HID; idx += 512) {
            int k = idx & 127, r = idx >> 7;
            int n = base + r; if (n >= NN) n = NN - 1;
            SM[k * PADI + r] = mean[(long)n * HID + k];
            SX[k * PADI + r] = xin[(long)n * HID + k];
        }
        __syncthreads();

        u64 bias = pack2(sb[j]);
        u64 a0 = bias, a1 = bias, a2 = bias, a3 = bias;

#pragma unroll 4
        for (int k = 0; k < HID; k++) {
            float wl = Sl[k * PADW + j];
            float wr = Sr[k * PADW + j];
            u64 wl2 = pack2(wl);
            u64 wr2 = pack2(wr);
            const ulonglong2* mp = reinterpret_cast<const ulonglong2*>(&SM[k * PADI + grp * 8]);
            const ulonglong2* xp = reinterpret_cast<const ulonglong2*>(&SX[k * PADI + grp * 8]);
            ulonglong2 mA = mp[0];
            ulonglong2 xA = xp[0];
            a0 = fma2(mA.x, wl2, a0); a0 = fma2(xA.x, wr2, a0);
            a1 = fma2(mA.y, wl2, a1); a1 = fma2(xA.y, wr2, a1);
            ulonglong2 mB = mp[1];
            ulonglong2 xB = xp[1];
            a2 = fma2(mB.x, wl2, a2); a2 = fma2(xB.x, wr2, a2);
            a3 = fma2(mB.y, wl2, a3); a3 = fma2(xB.y, wr2, a3);
        }

        int n0 = base + grp * 8;
        float lo, hi;
        unpack2(a0, lo, hi);
        if (n0 + 0 < NN) out[(long)(n0 + 0) * HID + j] = fmaxf(lo, 0.f);
        if (n0 + 1 < NN) out[(long)(n0 + 1) * HID + j] = fmaxf(hi, 0.f);
        unpack2(a1, lo, hi);
        if (n0 + 2 < NN) out[(long)(n0 + 2) * HID + j] = fmaxf(lo, 0.f);
        if (n0 + 3 < NN) out[(long)(n0 + 3) * HID + j] = fmaxf(hi, 0.f);
        unpack2(a2, lo, hi);
        if (n0 + 4 < NN) out[(long)(n0 + 4) * HID + j] = fmaxf(lo, 0.f);
        if (n0 + 5 < NN) out[(long)(n0 + 5) * HID + j] = fmaxf(hi, 0.f);
        unpack2(a3, lo, hi);
        if (n0 + 6 < NN) out[(long)(n0 + 6) * HID + j] = fmaxf(lo, 0.f);
        if (n0 + 7 < NN) out[(long)(n0 + 7) * HID + j] = fmaxf(hi, 0.f);
    }
}

// ---------------- segment pool: one block per graph ----------------
__global__ void pool_seg_kernel(const float* __restrict__ xf) {
    int g = blockIdx.x;
    int j = threadIdx.x;
    int n0 = g_goff[g], n1 = g_goff[g + 1];
    float acc = 0.f;
    int n = n0;
    for (; n + 4 <= n1; n += 4) {
        float v0 = xf[(long)(n + 0) * HID + j];
        float v1 = xf[(long)(n + 1) * HID + j];
        float v2 = xf[(long)(n + 2) * HID + j];
        float v3 = xf[(long)(n + 3) * HID + j];
        acc += (v0 + v1) + (v2 + v3);
    }
    for (; n < n1; n++) acc += xf[(long)n * HID + j];
    g_pool[g * HID + j] = acc;
}

// ---------------- MLP head ----------------
__global__ void mlp1_kernel(const float* __restrict__ W1, const float* __restrict__ b1) {
    int b = blockIdx.x;
    int j = threadIdx.x;
    __shared__ float sg[HID];
    sg[j] = fmaxf(g_pool[b * HID + j], 0.f);
    __syncthreads();
    float a = b1[j];
    const float* wrow = &W1[j * HID];
#pragma unroll 8
    for (int k = 0; k < HID; k++) a += sg[k] * wrow[k];
    g_h[b * HID + j] = fmaxf(a, 0.f);
}

__global__ void mlp2_kernel(const float* __restrict__ W2, const float* __restrict__ b2,
                            float* __restrict__ out) {
    int b = blockIdx.x;
    __shared__ float sh[HID];
    __shared__ float slog[NC];
    int tid = threadIdx.x;
    if (tid < HID) sh[tid] = g_h[b * HID + tid];
    __syncthreads();
    int w = tid >> 5, lane = tid & 31;
    if (w < NC) {
        float a = 0.f;
        for (int k = lane; k < HID; k += 32) a += sh[k] * W2[w * HID + k];
#pragma unroll
        for (int o = 16; o; o >>= 1) a += __shfl_down_sync(0xffffffffu, a, o);
        if (lane == 0) slog[w] = a + b2[w];
    }
    __syncthreads();
    if (tid < NC) {
        float mx = -1e30f;
#pragma unroll
        for (int c = 0; c < NC; c++) mx = fmaxf(mx, slog[c]);
        float se = 0.f;
#pragma unroll
        for (int c = 0; c < NC; c++) se += expf(slog[c] - mx);
        out[b * NC + tid] = slog[tid] - mx - logf(se);
    }
}

// ---------------- launch ----------------
extern "C" void kernel_launch(void* const* d_in, const int* in_sizes, int n_in,
                              void* d_out, int out_size) {
    const float* x     = (const float*)d_in[0];
    const int*   ei    = (const int*)d_in[2];
    const int*   batch = (const int*)d_in[3];
    const float* Wl    = (const float*)d_in[4];
    const float* bl    = (const float*)d_in[5];
    const float* Wr    = (const float*)d_in[6];
    const float* W1    = (const float*)d_in[7];
    const float* b1    = (const float*)d_in[8];
    const float* W2    = (const float*)d_in[9];
    const float* b2    = (const float*)d_in[10];
    float* out = (float*)d_out;

    float *mean_p, *x1_p, *x2_p;
    cudaGetSymbolAddress((void**)&mean_p, g_mean);
    cudaGetSymbolAddress((void**)&x1_p, g_x1);
    cudaGetSymbolAddress((void**)&x2_p, g_x2);

    const int SMEM_W = (2 * HID * PADW + 2 * HID * PADI) * (int)sizeof(float);  // ~166 KB
    cudaFuncSetAttribute(sage_gemm_kernel, cudaFuncAttributeMaxDynamicSharedMemorySize, SMEM_W);

    // CSR build + graph offsets
    zero_kernel<<<(NN + 255) / 256, 256>>>();
    count_kernel<<<(NE + 255) / 256, 256>>>(ei);
    gcount_kernel<<<(NN + 255) / 256, 256>>>(batch);
    scan_kernel<<<1, 1024>>>();
    gscan_kernel<<<1, 512>>>();
    bucket_kernel<<<(NE + 255) / 256, 256>>>(ei);

    const float* cur = x;
    float* nxt = x1_p;
    for (int l = 0; l < NL; l++) {
        aggregate_kernel<<<(NN * 32 + 255) / 256, 256>>>((const float4*)cur);
        sage_gemm_kernel<<<148, 512, SMEM_W>>>(mean_p, cur,
                                               Wl + l * HID * HID, bl + l * HID,
                                               Wr + l * HID * HID, nxt);
        cur = nxt;
        nxt = (cur == x1_p) ? x2_p : x1_p;
    }

    pool_seg_kernel<<<NG, HID>>>(cur);
    mlp1_kernel<<<NG, HID>>>(W1, b1);
    mlp2_kernel<<<NG, 320>>>(W2, b2, out);
}

// round 7
// speedup vs baseline: 1.6126x; 1.1037x over previous
#include <cuda_runtime.h>

#define NN 50000
#define NE 600000
#define NG 500
#define HID 128
#define NL 3
#define NC 10

#define TN 32          // gemm tile nodes
#define PADI 36        // staged-input row pad (floats), keeps 16B alignment, broadcast reads
#define PADW2 130      // staged-weight row pad (float2 elems)
#define NBLK 49        // scan blocks: ceil(50000/1024)

typedef unsigned long long u64;

// ---------------- scratch ----------------
__device__ float g_mean[NN * HID];
__device__ float g_x1[NN * HID];
__device__ float g_x2[NN * HID];
__device__ float g_pool[NG * HID];
__device__ float g_h[NG * HID];
__device__ int   g_deg[NN];
__device__ int   g_off[NN + 1];
__device__ int   g_cur[NN];
__device__ int   g_srcs[NE];
__device__ int   g_gcnt[NG];
__device__ int   g_goff[NG + 1];
__device__ int   g_bsum[NBLK];
__device__ int   g_bbase[NBLK];

// ---------------- f32x2 helpers ----------------
__device__ __forceinline__ u64 pack2(float a) {
    u64 r; asm("mov.b64 %0, {%1, %1};" : "=l"(r) : "f"(a)); return r;
}
__device__ __forceinline__ u64 fma2(u64 a, u64 b, u64 c) {
    u64 d; asm("fma.rn.f32x2 %0, %1, %2, %3;" : "=l"(d) : "l"(a), "l"(b), "l"(c)); return d;
}
__device__ __forceinline__ void unpack2(u64 v, float& lo, float& hi) {
    asm("mov.b64 {%0, %1}, %2;" : "=f"(lo), "=f"(hi) : "l"(v));
}

// ---------------- CSR build ----------------
__global__ void zero_kernel() {
    int i = blockIdx.x * blockDim.x + threadIdx.x;
    if (i < NN) g_deg[i] = 0;
    if (i < NG) g_gcnt[i] = 0;
}

// fused edge-degree count + per-graph node count
__global__ void count_kernel(const int* __restrict__ ei, const int* __restrict__ batch) {
    int e = blockIdx.x * blockDim.x + threadIdx.x;
    if (e < NE) atomicAdd(&g_deg[ei[NE + e]], 1);
    if (e < NN) atomicAdd(&g_gcnt[batch[e]], 1);
}

// phase 1: per-block inclusive scan of degrees; write local-exclusive + block sum
__global__ void scan1_kernel() {
    __shared__ int wsum[32];
    int tid = threadIdx.x, lane = tid & 31, w = tid >> 5;
    int i = blockIdx.x * 1024 + tid;
    int v = (i < NN) ? g_deg[i] : 0;
    int xs = v;
#pragma unroll
    for (int o = 1; o < 32; o <<= 1) {
        int t = __shfl_up_sync(0xffffffffu, xs, o);
        if (lane >= o) xs += t;
    }
    if (lane == 31) wsum[w] = xs;
    __syncthreads();
    if (w == 0) {
        int s = wsum[lane];
#pragma unroll
        for (int o = 1; o < 32; o <<= 1) {
            int t = __shfl_up_sync(0xffffffffu, s, o);
            if (lane >= o) s += t;
        }
        wsum[lane] = s;
    }
    __syncthreads();
    int base = (w > 0) ? wsum[w - 1] : 0;
    int incl = xs + base;
    if (i < NN) g_off[i] = incl - v;            // local exclusive
    if (tid == 1023) g_bsum[blockIdx.x] = incl; // block total
}

// phase 2: scan the 49 block sums (serial, tiny) + graph-offset scan (500 elems)
__global__ void scan2_kernel() {
    __shared__ int bs[NBLK];
    __shared__ int gs[512];
    int tid = threadIdx.x;
    if (tid < NBLK) bs[tid] = g_bsum[tid];
    int gv = (tid < NG) ? g_gcnt[tid] : 0;
    gs[tid] = gv;
    __syncthreads();
    if (tid == 0) {
        int r = 0;
        for (int i = 0; i < NBLK; i++) { int t = bs[i]; bs[i] = r; r += t; }
        g_off[NN] = r;
    }
    for (int o = 1; o < 512; o <<= 1) {
        int t = (tid >= o) ? gs[tid - o] : 0;
        __syncthreads();
        gs[tid] += t;
        __syncthreads();
    }
    if (tid < NG) g_goff[tid] = gs[tid] - gv;
    if (tid == NG - 1) g_goff[NG] = gs[tid];
    if (tid < NBLK) g_bbase[tid] = bs[tid];
}

// phase 3: add block bases
__global__ void scan3_kernel() {
    int i = blockIdx.x * 1024 + threadIdx.x;
    if (i >= NN) return;
    int v = g_off[i] + g_bbase[blockIdx.x];
    g_off[i] = v;
    g_cur[i] = v;
}

__global__ void bucket_kernel(const int* __restrict__ ei) {
    int e = blockIdx.x * blockDim.x + threadIdx.x;
    if (e >= NE) return;
    int src = ei[e];
    int dst = ei[NE + e];
    int pos = atomicAdd(&g_cur[dst], 1);
    g_srcs[pos] = src;
}

// ---------------- mean aggregation: one warp per node, MLP=4 ----------------
__global__ void aggregate_kernel(const float4* __restrict__ x) {
    int w = (blockIdx.x * blockDim.x + threadIdx.x) >> 5;
    int lane = threadIdx.x & 31;
    if (w >= NN) return;
    int s0 = g_off[w], s1 = g_off[w + 1];
    float4 a = make_float4(0.f, 0.f, 0.f, 0.f);
    int e = s0;
    for (; e + 4 <= s1; e += 4) {
        int i0 = __ldg(&g_srcs[e]);
        int i1 = __ldg(&g_srcs[e + 1]);
        int i2 = __ldg(&g_srcs[e + 2]);
        int i3 = __ldg(&g_srcs[e + 3]);
        float4 v0 = __ldg(&x[(long)i0 * 32 + lane]);
        float4 v1 = __ldg(&x[(long)i1 * 32 + lane]);
        float4 v2 = __ldg(&x[(long)i2 * 32 + lane]);
        float4 v3 = __ldg(&x[(long)i3 * 32 + lane]);
        a.x += (v0.x + v1.x) + (v2.x + v3.x);
        a.y += (v0.y + v1.y) + (v2.y + v3.y);
        a.z += (v0.z + v1.z) + (v2.z + v3.z);
        a.w += (v0.w + v1.w) + (v2.w + v3.w);
    }
    for (; e < s1; e++) {
        int s = __ldg(&g_srcs[e]);
        float4 v = __ldg(&x[(long)s * 32 + lane]);
        a.x += v.x; a.y += v.y; a.z += v.z; a.w += v.w;
    }
    float inv = 1.f / (float)max(s1 - s0, 1);
    float4 r = make_float4(a.x * inv, a.y * inv, a.z * inv, a.w * inv);
    reinterpret_cast<float4*>(g_mean)[(long)w * 32 + lane] = r;
}

// ---------------- fused SAGE GEMM with FFMA2 ----------------
// out[n][j] = relu( sum_k mean[n][k]*Wl[j][k] + bl[j] + sum_k x[n][k]*Wr[j][k] )
// 512 threads, 32-node tiles, 8 nodes/thread in 4 f32x2 accumulators.
// Weights interleaved (Wl,Wr) in float2 smem; input staging lane->row (conflict-free STS).
__global__ void __launch_bounds__(512) sage_gemm_kernel(
    const float* __restrict__ mean, const float* __restrict__ xin,
    const float* __restrict__ Wl, const float* __restrict__ bl,
    const float* __restrict__ Wr, float* __restrict__ out)
{
    extern __shared__ float smw[];
    float2* Sw = reinterpret_cast<float2*>(smw);      // [k*PADW2 + j] = (Wl[j][k], Wr[j][k])
    float*  SM = smw + 2 * HID * PADW2;               // [k*PADI + r]
    float*  SX = SM + HID * PADI;                     // [k*PADI + r]
    __shared__ float sb[HID];

    for (int idx = threadIdx.x; idx < HID * HID; idx += 512) {
        int j = idx >> 7, k = idx & 127;              // consecutive threads -> consecutive k (coalesced)
        Sw[k * PADW2 + j] = make_float2(Wl[idx], Wr[idx]);
    }
    if (threadIdx.x < HID) sb[threadIdx.x] = bl[threadIdx.x];
    __syncthreads();

    const int j = threadIdx.x & 127;
    const int grp = threadIdx.x >> 7;                 // 0..3 -> nodes grp*8 .. grp*8+7
    const int NT = (NN + TN - 1) / TN;                // 1563

    for (int tile = blockIdx.x; tile < NT; tile += gridDim.x) {
        int base = tile * TN;
        __syncthreads();
        // staging: lane -> row r, warp -> k-group; float4 loads, conflict-free STS
        for (int q = threadIdx.x; q < TN * (HID / 4); q += 512) {  // 1024, 2 iters
            int r = q & 31, kg = q >> 5;              // kg in 0..31
            int n = base + r; if (n >= NN) n = NN - 1;
            float4 m4 = __ldg(reinterpret_cast<const float4*>(&mean[(long)n * HID + kg * 4]));
            float4 x4 = __ldg(reinterpret_cast<const float4*>(&xin[(long)n * HID + kg * 4]));
            int k0 = kg * 4;
            SM[(k0 + 0) * PADI + r] = m4.x;
            SM[(k0 + 1) * PADI + r] = m4.y;
            SM[(k0 + 2) * PADI + r] = m4.z;
            SM[(k0 + 3) * PADI + r] = m4.w;
            SX[(k0 + 0) * PADI + r] = x4.x;
            SX[(k0 + 1) * PADI + r] = x4.y;
            SX[(k0 + 2) * PADI + r] = x4.z;
            SX[(k0 + 3) * PADI + r] = x4.w;
        }
        __syncthreads();

        u64 bias = pack2(sb[j]);
        u64 a0 = bias, a1 = bias, a2 = bias, a3 = bias;

#pragma unroll 4
        for (int k = 0; k < HID; k++) {
            float2 wpair = Sw[k * PADW2 + j];
            u64 wl2 = pack2(wpair.x);
            u64 wr2 = pack2(wpair.y);
            const ulonglong2* mp = reinterpret_cast<const ulonglong2*>(&SM[k * PADI + grp * 8]);
            const ulonglong2* xp = reinterpret_cast<const ulonglong2*>(&SX[k * PADI + grp * 8]);
            ulonglong2 mA = mp[0];
            ulonglong2 xA = xp[0];
            a0 = fma2(mA.x, wl2, a0); a0 = fma2(xA.x, wr2, a0);
            a1 = fma2(mA.y, wl2, a1); a1 = fma2(xA.y, wr2, a1);
            ulonglong2 mB = mp[1];
            ulonglong2 xB = xp[1];
            a2 = fma2(mB.x, wl2, a2); a2 = fma2(xB.x, wr2, a2);
            a3 = fma2(mB.y, wl2, a3); a3 = fma2(xB.y, wr2, a3);
        }

        int n0 = base + grp * 8;
        float lo, hi;
        unpack2(a0, lo, hi);
        if (n0 + 0 < NN) out[(long)(n0 + 0) * HID + j] = fmaxf(lo, 0.f);
        if (n0 + 1 < NN) out[(long)(n0 + 1) * HID + j] = fmaxf(hi, 0.f);
        unpack2(a1, lo, hi);
        if (n0 + 2 < NN) out[(long)(n0 + 2) * HID + j] = fmaxf(lo, 0.f);
        if (n0 + 3 < NN) out[(long)(n0 + 3) * HID + j] = fmaxf(hi, 0.f);
        unpack2(a2, lo, hi);
        if (n0 + 4 < NN) out[(long)(n0 + 4) * HID + j] = fmaxf(lo, 0.f);
        if (n0 + 5 < NN) out[(long)(n0 + 5) * HID + j] = fmaxf(hi, 0.f);
        unpack2(a3, lo, hi);
        if (n0 + 6 < NN) out[(long)(n0 + 6) * HID + j] = fmaxf(lo, 0.f);
        if (n0 + 7 < NN) out[(long)(n0 + 7) * HID + j] = fmaxf(hi, 0.f);
    }
}

// ---------------- segment pool: one block per graph ----------------
__global__ void pool_seg_kernel(const float* __restrict__ xf) {
    int g = blockIdx.x;
    int j = threadIdx.x;
    int n0 = g_goff[g], n1 = g_goff[g + 1];
    float acc = 0.f;
    int n = n0;
    for (; n + 4 <= n1; n += 4) {
        float v0 = xf[(long)(n + 0) * HID + j];
        float v1 = xf[(long)(n + 1) * HID + j];
        float v2 = xf[(long)(n + 2) * HID + j];
        float v3 = xf[(long)(n + 3) * HID + j];
        acc += (v0 + v1) + (v2 + v3);
    }
    for (; n < n1; n++) acc += xf[(long)n * HID + j];
    g_pool[g * HID + j] = acc;
}

// ---------------- MLP head ----------------
__global__ void mlp1_kernel(const float* __restrict__ W1, const float* __restrict__ b1) {
    int b = blockIdx.x;
    int j = threadIdx.x;
    __shared__ float sg[HID];
    sg[j] = fmaxf(g_pool[b * HID + j], 0.f);
    __syncthreads();
    float a = b1[j];
    const float* wrow = &W1[j * HID];
#pragma unroll 8
    for (int k = 0; k < HID; k++) a += sg[k] * wrow[k];
    g_h[b * HID + j] = fmaxf(a, 0.f);
}

__global__ void mlp2_kernel(const float* __restrict__ W2, const float* __restrict__ b2,
                            float* __restrict__ out) {
    int b = blockIdx.x;
    __shared__ float sh[HID];
    __shared__ float slog[NC];
    int tid = threadIdx.x;
    if (tid < HID) sh[tid] = g_h[b * HID + tid];
    __syncthreads();
    int w = tid >> 5, lane = tid & 31;
    if (w < NC) {
        float a = 0.f;
        for (int k = lane; k < HID; k += 32) a += sh[k] * W2[w * HID + k];
#pragma unroll
        for (int o = 16; o; o >>= 1) a += __shfl_down_sync(0xffffffffu, a, o);
        if (lane == 0) slog[w] = a + b2[w];
    }
    __syncthreads();
    if (tid < NC) {
        float mx = -1e30f;
#pragma unroll
        for (int c = 0; c < NC; c++) mx = fmaxf(mx, slog[c]);
        float se = 0.f;
#pragma unroll
        for (int c = 0; c < NC; c++) se += expf(slog[c] - mx);
        out[b * NC + tid] = slog[tid] - mx - logf(se);
    }
}

// ---------------- launch ----------------
extern "C" void kernel_launch(void* const* d_in, const int* in_sizes, int n_in,
                              void* d_out, int out_size) {
    const float* x     = (const float*)d_in[0];
    const int*   ei    = (const int*)d_in[2];
    const int*   batch = (const int*)d_in[3];
    const float* Wl    = (const float*)d_in[4];
    const float* bl    = (const float*)d_in[5];
    const float* Wr    = (const float*)d_in[6];
    const float* W1    = (const float*)d_in[7];
    const float* b1    = (const float*)d_in[8];
    const float* W2    = (const float*)d_in[9];
    const float* b2    = (const float*)d_in[10];
    float* out = (float*)d_out;

    float *mean_p, *x1_p, *x2_p;
    cudaGetSymbolAddress((void**)&mean_p, g_mean);
    cudaGetSymbolAddress((void**)&x1_p, g_x1);
    cudaGetSymbolAddress((void**)&x2_p, g_x2);

    const int SMEM_W = (2 * HID * PADW2 + 2 * HID * PADI) * (int)sizeof(float);  // ~170 KB
    cudaFuncSetAttribute(sage_gemm_kernel, cudaFuncAttributeMaxDynamicSharedMemorySize, SMEM_W);

    // CSR build + graph offsets (parallel scan)
    zero_kernel<<<(NN + 255) / 256, 256>>>();
    count_kernel<<<(NE + 255) / 256, 256>>>(ei, batch);
    scan1_kernel<<<NBLK, 1024>>>();
    scan2_kernel<<<1, 512>>>();
    scan3_kernel<<<NBLK, 1024>>>();
    bucket_kernel<<<(NE + 255) / 256, 256>>>(ei);

    const float* cur = x;
    float* nxt = x1_p;
    for (int l = 0; l < NL; l++) {
        aggregate_kernel<<<(NN * 32 + 255) / 256, 256>>>((const float4*)cur);
        sage_gemm_kernel<<<148, 512, SMEM_W>>>(mean_p, cur,
                                               Wl + l * HID * HID, bl + l * HID,
                                               Wr + l * HID * HID, nxt);
        cur = nxt;
        nxt = (cur == x1_p) ? x2_p : x1_p;
    }

    pool_seg_kernel<<<NG, HID>>>(cur);
    mlp1_kernel<<<NG, HID>>>(W1, b1);
    mlp2_kernel<<<NG, 320>>>(W2, b2, out);
}

// round 10
// speedup vs baseline: 1.9888x; 1.2333x over previous
#include <cuda_runtime.h>

#define NN 50000
#define NE 600000
#define NG 500
#define HID 128
#define NL 3
#define NC 10

#define TN 64          // gemm tile nodes
#define PADI 68        // staged-input row pad (floats), 16B-aligned
#define PADW2 129      // staged-weight row pad (float2 elems)
#define NBLK 49        // scan blocks: ceil(50000/1024)

typedef unsigned long long u64;

// ---------------- scratch ----------------
__device__ float g_mean[NN * HID];
__device__ float g_x1[NN * HID];
__device__ float g_x2[NN * HID];
__device__ int   g_deg[NN];
__device__ int   g_off[NN + 1];
__device__ int   g_cur[NN];
__device__ int   g_srcs[NE];
__device__ int   g_gcnt[NG];
__device__ int   g_goff[NG + 1];
__device__ int   g_bsum[NBLK];
__device__ int   g_bbase[NBLK];

// ---------------- f32x2 helpers ----------------
__device__ __forceinline__ u64 pack2(float a) {
    u64 r; asm("mov.b64 %0, {%1, %1};" : "=l"(r) : "f"(a)); return r;
}
__device__ __forceinline__ u64 fma2(u64 a, u64 b, u64 c) {
    u64 d; asm("fma.rn.f32x2 %0, %1, %2, %3;" : "=l"(d) : "l"(a), "l"(b), "l"(c)); return d;
}
__device__ __forceinline__ void unpack2(u64 v, float& lo, float& hi) {
    asm("mov.b64 {%0, %1}, %2;" : "=f"(lo), "=f"(hi) : "l"(v));
}

// ---------------- CSR build ----------------
__global__ void zero_kernel() {
    int i = blockIdx.x * blockDim.x + threadIdx.x;
    if (i < NN) g_deg[i] = 0;
    if (i < NG) g_gcnt[i] = 0;
}

__global__ void count_kernel(const int* __restrict__ ei, const int* __restrict__ batch) {
    int e = blockIdx.x * blockDim.x + threadIdx.x;
    if (e < NE) atomicAdd(&g_deg[ei[NE + e]], 1);
    if (e < NN) atomicAdd(&g_gcnt[batch[e]], 1);
}

__global__ void scan1_kernel() {
    __shared__ int wsum[32];
    int tid = threadIdx.x, lane = tid & 31, w = tid >> 5;
    int i = blockIdx.x * 1024 + tid;
    int v = (i < NN) ? g_deg[i] : 0;
    int xs = v;
#pragma unroll
    for (int o = 1; o < 32; o <<= 1) {
        int t = __shfl_up_sync(0xffffffffu, xs, o);
        if (lane >= o) xs += t;
    }
    if (lane == 31) wsum[w] = xs;
    __syncthreads();
    if (w == 0) {
        int s = wsum[lane];
#pragma unroll
        for (int o = 1; o < 32; o <<= 1) {
            int t = __shfl_up_sync(0xffffffffu, s, o);
            if (lane >= o) s += t;
        }
        wsum[lane] = s;
    }
    __syncthreads();
    int base = (w > 0) ? wsum[w - 1] : 0;
    int incl = xs + base;
    if (i < NN) g_off[i] = incl - v;
    if (tid == 1023) g_bsum[blockIdx.x] = incl;
}

__global__ void scan2_kernel() {
    __shared__ int bs[NBLK];
    __shared__ int gs[512];
    int tid = threadIdx.x;
    if (tid < NBLK) bs[tid] = g_bsum[tid];
    int gv = (tid < NG) ? g_gcnt[tid] : 0;
    gs[tid] = gv;
    __syncthreads();
    if (tid == 0) {
        int r = 0;
        for (int i = 0; i < NBLK; i++) { int t = bs[i]; bs[i] = r; r += t; }
        g_off[NN] = r;
    }
    for (int o = 1; o < 512; o <<= 1) {
        int t = (tid >= o) ? gs[tid - o] : 0;
        __syncthreads();
        gs[tid] += t;
        __syncthreads();
    }
    if (tid < NG) g_goff[tid] = gs[tid] - gv;
    if (tid == NG - 1) g_goff[NG] = gs[tid];
    if (tid < NBLK) g_bbase[tid] = bs[tid];
}

__global__ void scan3_kernel() {
    int i = blockIdx.x * 1024 + threadIdx.x;
    if (i >= NN) return;
    int v = g_off[i] + g_bbase[blockIdx.x];
    g_off[i] = v;
    g_cur[i] = v;
}

__global__ void bucket_kernel(const int* __restrict__ ei) {
    int e = blockIdx.x * blockDim.x + threadIdx.x;
    if (e >= NE) return;
    int src = ei[e];
    int dst = ei[NE + e];
    int pos = atomicAdd(&g_cur[dst], 1);
    g_srcs[pos] = src;
}

// ---------------- mean aggregation: one warp per node, MLP=4 ----------------
__global__ void aggregate_kernel(const float4* __restrict__ x) {
    int w = (blockIdx.x * blockDim.x + threadIdx.x) >> 5;
    int lane = threadIdx.x & 31;
    if (w >= NN) return;
    int s0 = g_off[w], s1 = g_off[w + 1];
    float4 a = make_float4(0.f, 0.f, 0.f, 0.f);
    int e = s0;
    for (; e + 4 <= s1; e += 4) {
        int i0 = __ldg(&g_srcs[e]);
        int i1 = __ldg(&g_srcs[e + 1]);
        int i2 = __ldg(&g_srcs[e + 2]);
        int i3 = __ldg(&g_srcs[e + 3]);
        float4 v0 = __ldg(&x[(long)i0 * 32 + lane]);
        float4 v1 = __ldg(&x[(long)i1 * 32 + lane]);
        float4 v2 = __ldg(&x[(long)i2 * 32 + lane]);
        float4 v3 = __ldg(&x[(long)i3 * 32 + lane]);
        a.x += (v0.x + v1.x) + (v2.x + v3.x);
        a.y += (v0.y + v1.y) + (v2.y + v3.y);
        a.z += (v0.z + v1.z) + (v2.z + v3.z);
        a.w += (v0.w + v1.w) + (v2.w + v3.w);
    }
    for (; e < s1; e++) {
        int s = __ldg(&g_srcs[e]);
        float4 v = __ldg(&x[(long)s * 32 + lane]);
        a.x += v.x; a.y += v.y; a.z += v.z; a.w += v.w;
    }
    float inv = 1.f / (float)max(s1 - s0, 1);
    float4 r = make_float4(a.x * inv, a.y * inv, a.z * inv, a.w * inv);
    reinterpret_cast<float4*>(g_mean)[(long)w * 32 + lane] = r;
}

// ---------------- fused SAGE GEMM with FFMA2, 2 j-columns x 8 nodes per thread ----
// out[n][j] = relu( sum_k mean[n][k]*Wl[j][k] + bl[j] + sum_k x[n][k]*Wr[j][k] )
// 512 threads: j = tid&63 (thread covers j and j+64), grp = tid>>6 (8 groups x 8 nodes).
__global__ void __launch_bounds__(512) sage_gemm_kernel(
    const float* __restrict__ mean, const float* __restrict__ xin,
    const float* __restrict__ Wl, const float* __restrict__ bl,
    const float* __restrict__ Wr, float* __restrict__ out)
{
    extern __shared__ float smw[];
    float2* Sw = reinterpret_cast<float2*>(smw);      // [k*PADW2 + j] = (Wl[j][k], Wr[j][k])
    float*  SM = smw + 2 * HID * PADW2;               // [k*PADI + r]
    float*  SX = SM + HID * PADI;                     // [k*PADI + r]
    __shared__ float sb[HID];

    for (int idx = threadIdx.x; idx < HID * HID; idx += 512) {
        int jw = idx >> 7, k = idx & 127;             // consecutive threads -> consecutive k (coalesced)
        Sw[k * PADW2 + jw] = make_float2(Wl[idx], Wr[idx]);
    }
    if (threadIdx.x < HID) sb[threadIdx.x] = bl[threadIdx.x];
    __syncthreads();

    const int j  = threadIdx.x & 63;
    const int j2 = j + 64;
    const int grp = threadIdx.x >> 6;                 // 0..7 -> nodes grp*8 .. grp*8+7
    const int NT = (NN + TN - 1) / TN;                // 782

    for (int tile = blockIdx.x; tile < NT; tile += gridDim.x) {
        int base = tile * TN;
        __syncthreads();
        // staging: q -> (r = q&63, kg = q>>6); float4 gmem loads, conflict-free STS
        for (int q = threadIdx.x; q < TN * (HID / 4); q += 512) {  // 2048, 4 iters
            int r = q & 63, kg = q >> 6;              // kg in 0..31
            int n = base + r; if (n >= NN) n = NN - 1;
            float4 m4 = __ldg(reinterpret_cast<const float4*>(&mean[(long)n * HID + kg * 4]));
            float4 x4 = __ldg(reinterpret_cast<const float4*>(&xin[(long)n * HID + kg * 4]));
            int k0 = kg * 4;
            SM[(k0 + 0) * PADI + r] = m4.x;
            SM[(k0 + 1) * PADI + r] = m4.y;
            SM[(k0 + 2) * PADI + r] = m4.z;
            SM[(k0 + 3) * PADI + r] = m4.w;
            SX[(k0 + 0) * PADI + r] = x4.x;
            SX[(k0 + 1) * PADI + r] = x4.y;
            SX[(k0 + 2) * PADI + r] = x4.z;
            SX[(k0 + 3) * PADI + r] = x4.w;
        }
        __syncthreads();

        u64 biasA = pack2(sb[j]);
        u64 biasB = pack2(sb[j2]);
        u64 a0 = biasA, a1 = biasA, a2 = biasA, a3 = biasA;   // j, nodes 0..7
        u64 b0 = biasB, b1 = biasB, b2 = biasB, b3 = biasB;   // j+64, nodes 0..7

#pragma unroll 4
        for (int k = 0; k < HID; k++) {
            float2 wpA = Sw[k * PADW2 + j];
            float2 wpB = Sw[k * PADW2 + j2];
            u64 wlA = pack2(wpA.x), wrA = pack2(wpA.y);
            u64 wlB = pack2(wpB.x), wrB = pack2(wpB.y);
            const ulonglong2* mp = reinterpret_cast<const ulonglong2*>(&SM[k * PADI + grp * 8]);
            const ulonglong2* xp = reinterpret_cast<const ulonglong2*>(&SX[k * PADI + grp * 8]);
            ulonglong2 mA = mp[0];
            ulonglong2 mB = mp[1];
            ulonglong2 xA = xp[0];
            ulonglong2 xB = xp[1];
            a0 = fma2(mA.x, wlA, a0); a1 = fma2(mA.y, wlA, a1);
            a2 = fma2(mB.x, wlA, a2); a3 = fma2(mB.y, wlA, a3);
            a0 = fma2(xA.x, wrA, a0); a1 = fma2(xA.y, wrA, a1);
            a2 = fma2(xB.x, wrA, a2); a3 = fma2(xB.y, wrA, a3);
            b0 = fma2(mA.x, wlB, b0); b1 = fma2(mA.y, wlB, b1);
            b2 = fma2(mB.x, wlB, b2); b3 = fma2(mB.y, wlB, b3);
            b0 = fma2(xA.x, wrB, b0); b1 = fma2(xA.y, wrB, b1);
            b2 = fma2(xB.x, wrB, b2); b3 = fma2(xB.y, wrB, b3);
        }

        int n0 = base + grp * 8;
        float lo, hi;
        if (n0 + 7 < NN) {
            unpack2(a0, lo, hi);
            out[(long)(n0 + 0) * HID + j] = fmaxf(lo, 0.f);
            out[(long)(n0 + 1) * HID + j] = fmaxf(hi, 0.f);
            unpack2(a1, lo, hi);
            out[(long)(n0 + 2) * HID + j] = fmaxf(lo, 0.f);
            out[(long)(n0 + 3) * HID + j] = fmaxf(hi, 0.f);
            unpack2(a2, lo, hi);
            out[(long)(n0 + 4) * HID + j] = fmaxf(lo, 0.f);
            out[(long)(n0 + 5) * HID + j] = fmaxf(hi, 0.f);
            unpack2(a3, lo, hi);
            out[(long)(n0 + 6) * HID + j] = fmaxf(lo, 0.f);
            out[(long)(n0 + 7) * HID + j] = fmaxf(hi, 0.f);
            unpack2(b0, lo, hi);
            out[(long)(n0 + 0) * HID + j2] = fmaxf(lo, 0.f);
            out[(long)(n0 + 1) * HID + j2] = fmaxf(hi, 0.f);
            unpack2(b1, lo, hi);
            out[(long)(n0 + 2) * HID + j2] = fmaxf(lo, 0.f);
            out[(long)(n0 + 3) * HID + j2] = fmaxf(hi, 0.f);
            unpack2(b2, lo, hi);
            out[(long)(n0 + 4) * HID + j2] = fmaxf(lo, 0.f);
            out[(long)(n0 + 5) * HID + j2] = fmaxf(hi, 0.f);
            unpack2(b3, lo, hi);
            out[(long)(n0 + 6) * HID + j2] = fmaxf(lo, 0.f);
            out[(long)(n0 + 7) * HID + j2] = fmaxf(hi, 0.f);
        } else {
            u64 av[4] = {a0, a1, a2, a3};
            u64 bv[4] = {b0, b1, b2, b3};
            for (int p = 0; p < 4; p++) {
                unpack2(av[p], lo, hi);
                if (n0 + 2 * p     < NN) out[(long)(n0 + 2 * p)     * HID + j] = fmaxf(lo, 0.f);
                if (n0 + 2 * p + 1 < NN) out[(long)(n0 + 2 * p + 1) * HID + j] = fmaxf(hi, 0.f);
                unpack2(bv[p], lo, hi);
                if (n0 + 2 * p     < NN) out[(long)(n0 + 2 * p)     * HID + j2] = fmaxf(lo, 0.f);
                if (n0 + 2 * p + 1 < NN) out[(long)(n0 + 2 * p + 1) * HID + j2] = fmaxf(hi, 0.f);
            }
        }
    }
}

// ---------------- fused tail: pool + relu + mlp1 + mlp2 + log_softmax ----------------
__global__ void tail_kernel(const float* __restrict__ xf,
                            const float* __restrict__ W1, const float* __restrict__ b1,
                            const float* __restrict__ W2, const float* __restrict__ b2,
                            float* __restrict__ out) {
    int g = blockIdx.x;
    int j = threadIdx.x;         // 128 threads
    __shared__ float sg[HID];
    __shared__ float sh[HID];
    __shared__ float slog[NC];

    // pool (segment sum over sorted batch)
    int n0 = g_goff[g], n1 = g_goff[g + 1];
    float acc = 0.f;
    int n = n0;
    for (; n + 4 <= n1; n += 4) {
        float v0 = xf[(long)(n + 0) * HID + j];
        float v1 = xf[(long)(n + 1) * HID + j];
        float v2 = xf[(long)(n + 2) * HID + j];
        float v3 = xf[(long)(n + 3) * HID + j];
        acc += (v0 + v1) + (v2 + v3);
    }
    for (; n < n1; n++) acc += xf[(long)n * HID + j];
    sg[j] = fmaxf(acc, 0.f);
    __syncthreads();

    // mlp1
    float a = b1[j];
    const float* wrow = &W1[j * HID];
#pragma unroll 8
    for (int k = 0; k < HID; k++) a += sg[k] * wrow[k];
    sh[j] = fmaxf(a, 0.f);
    __syncthreads();

    // mlp2: 4 warps, warp w handles classes w, w+4, w+8
    int w = j >> 5, lane = j & 31;
    for (int c = w; c < NC; c += 4) {
        float s = 0.f;
        for (int k = lane; k < HID; k += 32) s += sh[k] * W2[c * HID + k];
#pragma unroll
        for (int o = 16; o; o >>= 1) s += __shfl_down_sync(0xffffffffu, s, o);
        if (lane == 0) slog[c] = s + b2[c];
    }
    __syncthreads();

    // log_softmax
    if (j < NC) {
        float mx = -1e30f;
#pragma unroll
        for (int c = 0; c < NC; c++) mx = fmaxf(mx, slog[c]);
        float se = 0.f;
#pragma unroll
        for (int c = 0; c < NC; c++) se += expf(slog[c] - mx);
        out[g * NC + j] = slog[j] - mx - logf(se);
    }
}

// ---------------- launch ----------------
extern "C" void kernel_launch(void* const* d_in, const int* in_sizes, int n_in,
                              void* d_out, int out_size) {
    const float* x     = (const float*)d_in[0];
    const int*   ei    = (const int*)d_in[2];
    const int*   batch = (const int*)d_in[3];
    const float* Wl    = (const float*)d_in[4];
    const float* bl    = (const float*)d_in[5];
    const float* Wr    = (const float*)d_in[6];
    const float* W1    = (const float*)d_in[7];
    const float* b1    = (const float*)d_in[8];
    const float* W2    = (const float*)d_in[9];
    const float* b2    = (const float*)d_in[10];
    float* out = (float*)d_out;

    float *mean_p, *x1_p, *x2_p;
    cudaGetSymbolAddress((void**)&mean_p, g_mean);
    cudaGetSymbolAddress((void**)&x1_p, g_x1);
    cudaGetSymbolAddress((void**)&x2_p, g_x2);

    const int SMEM_W = (2 * HID * PADW2 + 2 * HID * PADI) * (int)sizeof(float);  // ~202 KB
    cudaFuncSetAttribute(sage_gemm_kernel, cudaFuncAttributeMaxDynamicSharedMemorySize, SMEM_W);

    zero_kernel<<<(NN + 255) / 256, 256>>>();
    count_kernel<<<(NE + 255) / 256, 256>>>(ei, batch);
    scan1_kernel<<<NBLK, 1024>>>();
    scan2_kernel<<<1, 512>>>();
    scan3_kernel<<<NBLK, 1024>>>();
    bucket_kernel<<<(NE + 255) / 256, 256>>>(ei);

    const float* cur = x;
    float* nxt = x1_p;
    for (int l = 0; l < NL; l++) {
        aggregate_kernel<<<(NN * 32 + 255) / 256, 256>>>((const float4*)cur);
        sage_gemm_kernel<<<148, 512, SMEM_W>>>(mean_p, cur,
                                               Wl + l * HID * HID, bl + l * HID,
                                               Wr + l * HID * HID, nxt);
        cur = nxt;
        nxt = (cur == x1_p) ? x2_p : x1_p;
    }

    tail_kernel<<<NG, HID>>>(cur, W1, b1, W2, b2, out);
}

// round 12
// speedup vs baseline: 3.2850x; 1.6518x over previous
#include <cuda_runtime.h>
#include <cuda_bf16.h>
#include <cstdint>

#define NN 50000
#define NE 600000
#define NG 500
#define HID 128
#define NL 3
#define NC 10
#define NBLK 49        // scan blocks: ceil(50000/1024)

typedef unsigned long long u64;

// ---------------- scratch ----------------
__device__ float g_mean[NN * HID];
__device__ float g_x1[NN * HID];
__device__ float g_x2[NN * HID];
__device__ int   g_deg[NN];
__device__ int   g_off[NN + 1];
__device__ int   g_cur[NN];
__device__ int   g_srcs[NE];
__device__ int   g_gcnt[NG];
__device__ int   g_goff[NG + 1];
__device__ int   g_bsum[NBLK];
__device__ int   g_bbase[NBLK];

// ---------------- PTX helpers (all plain sm_80+; no 'a'-gated features) ----------------
__device__ __forceinline__ uint32_t smem_u32(const void* p) {
    uint32_t a;
    asm("{ .reg .u64 t; cvta.to.shared.u64 t, %1; cvt.u32.u64 %0, t; }" : "=r"(a) : "l"(p));
    return a;
}
__device__ __forceinline__ void ldsm4(uint32_t* r, uint32_t addr) {
    asm volatile("ldmatrix.sync.aligned.m8n8.x4.shared.b16 {%0,%1,%2,%3}, [%4];"
                 : "=r"(r[0]), "=r"(r[1]), "=r"(r[2]), "=r"(r[3]) : "r"(addr));
}
__device__ __forceinline__ void mma16816(float* c, const uint32_t* a, uint32_t b0, uint32_t b1) {
    asm volatile("mma.sync.aligned.m16n8k16.row.col.f32.bf16.bf16.f32 "
                 "{%0,%1,%2,%3}, {%4,%5,%6,%7}, {%8,%9}, {%0,%1,%2,%3};"
                 : "+f"(c[0]), "+f"(c[1]), "+f"(c[2]), "+f"(c[3])
                 : "r"(a[0]), "r"(a[1]), "r"(a[2]), "r"(a[3]), "r"(b0), "r"(b1));
}

// smem layout (bytes).  A half-tile: 128 rows x 136 bf16 (272B stride, pad 8 -> LDSM conflict-free).
// B: 128 j x 264 bf16 (528B stride, K=256 + pad 8).
#define S_BIAS 0
#define S_AH   512
#define S_AL   (S_AH + 128 * 272)
#define S_BH   (S_AL + 128 * 272)
#define S_BL   (S_BH + 128 * 528)
#define S_TOTAL (S_BL + 128 * 528)   // 205312 bytes

// ---------------- CSR build ----------------
__global__ void zero_kernel() {
    int i = blockIdx.x * blockDim.x + threadIdx.x;
    if (i < NN) g_deg[i] = 0;
    if (i < NG) g_gcnt[i] = 0;
}

__global__ void count_kernel(const int* __restrict__ ei, const int* __restrict__ batch) {
    int e = blockIdx.x * blockDim.x + threadIdx.x;
    if (e < NE) atomicAdd(&g_deg[ei[NE + e]], 1);
    if (e < NN) atomicAdd(&g_gcnt[batch[e]], 1);
}

__global__ void scan1_kernel() {
    __shared__ int wsum[32];
    int tid = threadIdx.x, lane = tid & 31, w = tid >> 5;
    int i = blockIdx.x * 1024 + tid;
    int v = (i < NN) ? g_deg[i] : 0;
    int xs = v;
#pragma unroll
    for (int o = 1; o < 32; o <<= 1) {
        int t = __shfl_up_sync(0xffffffffu, xs, o);
        if (lane >= o) xs += t;
    }
    if (lane == 31) wsum[w] = xs;
    __syncthreads();
    if (w == 0) {
        int s = wsum[lane];
#pragma unroll
        for (int o = 1; o < 32; o <<= 1) {
            int t = __shfl_up_sync(0xffffffffu, s, o);
            if (lane >= o) s += t;
        }
        wsum[lane] = s;
    }
    __syncthreads();
    int base = (w > 0) ? wsum[w - 1] : 0;
    int incl = xs + base;
    if (i < NN) g_off[i] = incl - v;
    if (tid == 1023) g_bsum[blockIdx.x] = incl;
}

__global__ void scan2_kernel() {
    __shared__ int bs[NBLK];
    __shared__ int gs[512];
    int tid = threadIdx.x;
    if (tid < NBLK) bs[tid] = g_bsum[tid];
    int gv = (tid < NG) ? g_gcnt[tid] : 0;
    gs[tid] = gv;
    __syncthreads();
    if (tid == 0) {
        int r = 0;
        for (int i = 0; i < NBLK; i++) { int t = bs[i]; bs[i] = r; r += t; }
        g_off[NN] = r;
    }
    for (int o = 1; o < 512; o <<= 1) {
        int t = (tid >= o) ? gs[tid - o] : 0;
        __syncthreads();
        gs[tid] += t;
        __syncthreads();
    }
    if (tid < NG) g_goff[tid] = gs[tid] - gv;
    if (tid == NG - 1) g_goff[NG] = gs[tid];
    if (tid < NBLK) g_bbase[tid] = bs[tid];
}

__global__ void scan3_kernel() {
    int i = blockIdx.x * 1024 + threadIdx.x;
    if (i >= NN) return;
    int v = g_off[i] + g_bbase[blockIdx.x];
    g_off[i] = v;
    g_cur[i] = v;
}

__global__ void bucket_kernel(const int* __restrict__ ei) {
    int e = blockIdx.x * blockDim.x + threadIdx.x;
    if (e >= NE) return;
    int src = ei[e];
    int dst = ei[NE + e];
    int pos = atomicAdd(&g_cur[dst], 1);
    g_srcs[pos] = src;
}

// ---------------- mean aggregation: one warp per node, MLP=4 ----------------
__global__ void aggregate_kernel(const float4* __restrict__ x) {
    int w = (blockIdx.x * blockDim.x + threadIdx.x) >> 5;
    int lane = threadIdx.x & 31;
    if (w >= NN) return;
    int s0 = g_off[w], s1 = g_off[w + 1];
    float4 a = make_float4(0.f, 0.f, 0.f, 0.f);
    int e = s0;
    for (; e + 4 <= s1; e += 4) {
        int i0 = __ldg(&g_srcs[e]);
        int i1 = __ldg(&g_srcs[e + 1]);
        int i2 = __ldg(&g_srcs[e + 2]);
        int i3 = __ldg(&g_srcs[e + 3]);
        float4 v0 = __ldg(&x[(long)i0 * 32 + lane]);
        float4 v1 = __ldg(&x[(long)i1 * 32 + lane]);
        float4 v2 = __ldg(&x[(long)i2 * 32 + lane]);
        float4 v3 = __ldg(&x[(long)i3 * 32 + lane]);
        a.x += (v0.x + v1.x) + (v2.x + v3.x);
        a.y += (v0.y + v1.y) + (v2.y + v3.y);
        a.z += (v0.z + v1.z) + (v2.z + v3.z);
        a.w += (v0.w + v1.w) + (v2.w + v3.w);
    }
    for (; e < s1; e++) {
        int s = __ldg(&g_srcs[e]);
        float4 v = __ldg(&x[(long)s * 32 + lane]);
        a.x += v.x; a.y += v.y; a.z += v.z; a.w += v.w;
    }
    float inv = 1.f / (float)max(s1 - s0, 1);
    float4 r = make_float4(a.x * inv, a.y * inv, a.z * inv, a.w * inv);
    reinterpret_cast<float4*>(g_mean)[(long)w * 32 + lane] = r;
}

// -------- hi/lo bf16 split of a float4 -> two u64 (4 bf16 each) --------
__device__ __forceinline__ void split4(float4 v, u64& hi, u64& lo) {
    __nv_bfloat162 h01 = __floats2bfloat162_rn(v.x, v.y);
    __nv_bfloat162 h23 = __floats2bfloat162_rn(v.z, v.w);
    float rx = v.x - __bfloat162float(__low2bfloat16(h01));
    float ry = v.y - __bfloat162float(__high2bfloat16(h01));
    float rz = v.z - __bfloat162float(__low2bfloat16(h23));
    float rw = v.w - __bfloat162float(__high2bfloat16(h23));
    __nv_bfloat162 l01 = __floats2bfloat162_rn(rx, ry);
    __nv_bfloat162 l23 = __floats2bfloat162_rn(rz, rw);
    uint32_t a = *reinterpret_cast<uint32_t*>(&h01);
    uint32_t b = *reinterpret_cast<uint32_t*>(&h23);
    uint32_t c = *reinterpret_cast<uint32_t*>(&l01);
    uint32_t d = *reinterpret_cast<uint32_t*>(&l23);
    hi = (u64)a | ((u64)b << 32);
    lo = (u64)c | ((u64)d << 32);
}

// ---------------- HMMA SAGE GEMM ----------------
// D[128 nodes][128 j] = [mean|x](K=256, hi/lo bf16) @ [Wl|Wr]^T ; relu(D + bl) -> out
// 8 warps: warp = (row-group 0..3: 32 rows) x (col-group 0..1: 64 j).
__global__ void __launch_bounds__(256, 1)
mma_gemm_kernel(const float* __restrict__ mean, const float* __restrict__ xin,
                const float* __restrict__ Wl, const float* __restrict__ bl,
                const float* __restrict__ Wr, float* __restrict__ out)
{
    extern __shared__ __align__(16) char smem[];
    const uint32_t sb32 = smem_u32(smem);
    const int tid = threadIdx.x;
    const int wid = tid >> 5;
    const int lane = tid & 31;
    const int g = lane >> 2, tg = lane & 3;
    const int rowbase = (wid & 3) * 32;
    const int colbase = (wid >> 2) * 64;
    float* bias = reinterpret_cast<float*>(smem + S_BIAS);

    // ---- stage weights (hi/lo) once: B[j][k], j row stride 264 bf16 (528B) ----
    for (int idx = tid; idx < 2 * 128 * 32; idx += 256) {
        int mat = idx >> 12;                 // 0=Wl (k 0..127), 1=Wr (k 128..255)
        int rem = idx & 4095;
        int r = rem >> 5, kg = rem & 31;
        const float* W = mat ? Wr : Wl;
        float4 v = __ldg(reinterpret_cast<const float4*>(&W[r * HID + kg * 4]));
        u64 hi, lo;
        split4(v, hi, lo);
        uint32_t off = (uint32_t)(r * 528 + mat * 256 + kg * 8);
        *reinterpret_cast<u64*>(smem + S_BH + off) = hi;
        *reinterpret_cast<u64*>(smem + S_BL + off) = lo;
    }
    if (tid < HID) bias[tid] = bl[tid];
    __syncthreads();

    // per-lane ldmatrix base offsets
    const uint32_t laneA = (uint32_t)((lane & 15) * 272 + ((lane >> 4) & 1) * 16);
    const uint32_t laneB = (uint32_t)((colbase + (lane & 7) + ((lane >> 4) & 1) * 8) * 528
                                      + ((lane >> 3) & 1) * 16);

    const int NT = (NN + 127) / 128;         // 391
    for (int tile = blockIdx.x; tile < NT; tile += gridDim.x) {
        const int base = tile * 128;
        float acc[2][8][4];
#pragma unroll
        for (int mb = 0; mb < 2; mb++)
#pragma unroll
            for (int nt = 0; nt < 8; nt++)
#pragma unroll
                for (int q = 0; q < 4; q++) acc[mb][nt][q] = 0.f;

#pragma unroll
        for (int half = 0; half < 2; half++) {
            // stage A half (hi/lo): 128 rows x 128 k, row stride 136 bf16 (272B)
            const float* src = half ? xin : mean;
            for (int idx = tid; idx < 128 * 32; idx += 256) {
                int r = idx >> 5, kg = idx & 31;
                int n = base + r; if (n >= NN) n = NN - 1;
                float4 v = __ldg(reinterpret_cast<const float4*>(&src[(long)n * HID + kg * 4]));
                u64 hi, lo;
                split4(v, hi, lo);
                uint32_t off = (uint32_t)(r * 272 + kg * 8);
                *reinterpret_cast<u64*>(smem + S_AH + off) = hi;
                *reinterpret_cast<u64*>(smem + S_AL + off) = lo;
            }
            __syncthreads();

            const uint32_t kbyte = (uint32_t)(half * 256);   // B col byte offset (128 bf16)
#pragma unroll
            for (int term = 0; term < 3; term++) {
                uint32_t Ab = sb32 + (term == 2 ? S_AL : S_AH) + rowbase * 272 + laneA;
                uint32_t Bb = sb32 + (term == 1 ? S_BL : S_BH) + laneB + kbyte;
#pragma unroll
                for (int ks = 0; ks < 8; ks++) {
                    uint32_t aF[2][4];
                    ldsm4(aF[0], Ab + ks * 32);
                    ldsm4(aF[1], Ab + 16 * 272 + ks * 32);
                    uint32_t bF[4][4];
#pragma unroll
                    for (int np = 0; np < 4; np++)
                        ldsm4(bF[np], Bb + np * 16 * 528 + ks * 32);
#pragma unroll
                    for (int mb = 0; mb < 2; mb++)
#pragma unroll
                        for (int np = 0; np < 4; np++) {
                            mma16816(acc[mb][np * 2 + 0], aF[mb], bF[np][0], bF[np][1]);
                            mma16816(acc[mb][np * 2 + 1], aF[mb], bF[np][2], bF[np][3]);
                        }
                }
            }
            __syncthreads();   // A smem free before restage / next tile
        }

        // ---- epilogue: bias + relu, float2 stores ----
#pragma unroll
        for (int mb = 0; mb < 2; mb++) {
            int r0 = base + rowbase + mb * 16 + g;
            int r1 = r0 + 8;
#pragma unroll
            for (int nt = 0; nt < 8; nt++) {
                int col = colbase + nt * 8 + 2 * tg;
                float2 bv = *reinterpret_cast<const float2*>(&bias[col]);
                float* c = acc[mb][nt];
                if (r0 < NN) {
                    float2 o = make_float2(fmaxf(c[0] + bv.x, 0.f), fmaxf(c[1] + bv.y, 0.f));
                    *reinterpret_cast<float2*>(&out[(long)r0 * HID + col]) = o;
                }
                if (r1 < NN) {
                    float2 o = make_float2(fmaxf(c[2] + bv.x, 0.f), fmaxf(c[3] + bv.y, 0.f));
                    *reinterpret_cast<float2*>(&out[(long)r1 * HID + col]) = o;
                }
            }
        }
    }
}

// ---------------- fused tail: pool + relu + mlp1 + mlp2 + log_softmax ----------------
__global__ void tail_kernel(const float* __restrict__ xf,
                            const float* __restrict__ W1, const float* __restrict__ b1,
                            const float* __restrict__ W2, const float* __restrict__ b2,
                            float* __restrict__ out) {
    int g = blockIdx.x;
    int j = threadIdx.x;
    __shared__ float sg[HID];
    __shared__ float sh[HID];
    __shared__ float slog[NC];

    int n0 = g_goff[g], n1 = g_goff[g + 1];
    float acc = 0.f;
    int n = n0;
    for (; n + 4 <= n1; n += 4) {
        float v0 = xf[(long)(n + 0) * HID + j];
        float v1 = xf[(long)(n + 1) * HID + j];
        float v2 = xf[(long)(n + 2) * HID + j];
        float v3 = xf[(long)(n + 3) * HID + j];
        acc += (v0 + v1) + (v2 + v3);
    }
    for (; n < n1; n++) acc += xf[(long)n * HID + j];
    sg[j] = fmaxf(acc, 0.f);
    __syncthreads();

    float a = b1[j];
    const float* wrow = &W1[j * HID];
#pragma unroll 8
    for (int k = 0; k < HID; k++) a += sg[k] * wrow[k];
    sh[j] = fmaxf(a, 0.f);
    __syncthreads();

    int w = j >> 5, lane = j & 31;
    for (int c = w; c < NC; c += 4) {
        float s = 0.f;
        for (int k = lane; k < HID; k += 32) s += sh[k] * W2[c * HID + k];
#pragma unroll
        for (int o = 16; o; o >>= 1) s += __shfl_down_sync(0xffffffffu, s, o);
        if (lane == 0) slog[c] = s + b2[c];
    }
    __syncthreads();

    if (j < NC) {
        float mx = -1e30f;
#pragma unroll
        for (int c = 0; c < NC; c++) mx = fmaxf(mx, slog[c]);
        float se = 0.f;
#pragma unroll
        for (int c = 0; c < NC; c++) se += expf(slog[c] - mx);
        out[g * NC + j] = slog[j] - mx - logf(se);
    }
}

// ---------------- launch ----------------
extern "C" void kernel_launch(void* const* d_in, const int* in_sizes, int n_in,
                              void* d_out, int out_size) {
    const float* x     = (const float*)d_in[0];
    const int*   ei    = (const int*)d_in[2];
    const int*   batch = (const int*)d_in[3];
    const float* Wl    = (const float*)d_in[4];
    const float* bl    = (const float*)d_in[5];
    const float* Wr    = (const float*)d_in[6];
    const float* W1    = (const float*)d_in[7];
    const float* b1    = (const float*)d_in[8];
    const float* W2    = (const float*)d_in[9];
    const float* b2    = (const float*)d_in[10];
    float* out = (float*)d_out;

    float *mean_p, *x1_p, *x2_p;
    cudaGetSymbolAddress((void**)&mean_p, g_mean);
    cudaGetSymbolAddress((void**)&x1_p, g_x1);
    cudaGetSymbolAddress((void**)&x2_p, g_x2);

    cudaFuncSetAttribute(mma_gemm_kernel, cudaFuncAttributeMaxDynamicSharedMemorySize, S_TOTAL);

    zero_kernel<<<(NN + 255) / 256, 256>>>();
    count_kernel<<<(NE + 255) / 256, 256>>>(ei, batch);
    scan1_kernel<<<NBLK, 1024>>>();
    scan2_kernel<<<1, 512>>>();
    scan3_kernel<<<NBLK, 1024>>>();
    bucket_kernel<<<(NE + 255) / 256, 256>>>(ei);

    const float* cur = x;
    float* nxt = x1_p;
    for (int l = 0; l < NL; l++) {
        aggregate_kernel<<<(NN * 32 + 255) / 256, 256>>>((const float4*)cur);
        mma_gemm_kernel<<<148, 256, S_TOTAL>>>(mean_p, cur,
                                               Wl + l * HID * HID, bl + l * HID,
                                               Wr + l * HID * HID, nxt);
        cur = nxt;
        nxt = (cur == x1_p) ? x2_p : x1_p;
    }

    tail_kernel<<<NG, HID>>>(cur, W1, b1, W2, b2, out);
}